// round 17
// baseline (speedup 1.0000x reference)
#include <cuda_runtime.h>
#include <cuda_bf16.h>

// CTC forward, two tasks (PyTorch semantics: blank=0, mean of loss/target_len,
// zero_infinity). One block per (task, batch) = 64 blocks x 64 threads (2 warps).
//
// Two-warp skewed wavefront, 8 slots/thread, block-float-per-thread state
// (8 fp32 mantissas + one int32 exponent), renormalized every 8 steps.
// No block barriers in the scan:
//  - each warp privately computes softmax probs (ex2 + butterfly + rcp) into
//    its own smem double buffer (2 STS; 5 LDS gathers prefetched 1 step ahead)
//  - single cross-warp operand (warp0 lane31 slot7) via full-depth write-once
//    volatile ring; sentinel = sign bit forced on published mantissa bits.

#define LOG2E 1.4426950408889634f
#define LN2   0.6931471805599453f
#define BATCH 32
#define TMAX  2000
#define NT    64
#define NSLOT 8
#define NSYM  4
#define EMIN  (-(1 << 28))
#define DYNSMEM (TMAX * 8)   // ring: uint2[TMAX]

static __device__ float        g_partial[64];
static __device__ unsigned int g_count = 0;

__device__ __forceinline__ float ex2(float x) {
    float y; asm("ex2.approx.f32 %0, %1;" : "=f"(y) : "f"(x)); return y;
}
__device__ __forceinline__ float lg2(float x) {
    float y; asm("lg2.approx.f32 %0, %1;" : "=f"(y) : "f"(x)); return y;
}
__device__ __forceinline__ float rcpf(float x) {
    float y; asm("rcp.approx.f32 %0, %1;" : "=f"(y) : "f"(x)); return y;
}
__device__ __forceinline__ float pow2c(int dp127) {   // 2^d, clamped both ends
    return __int_as_float(min(max(dp127, 0), 254) << 23);
}

__global__ void __launch_bounds__(NT, 1)
ctc_forward_kernel(const float* __restrict__ elog, const float* __restrict__ plog,
                   const int* __restrict__ etgt, const int* __restrict__ ptgt,
                   const int* __restrict__ eil,  const int* __restrict__ pil,
                   const int* __restrict__ etl,  const int* __restrict__ ptl,
                   float* __restrict__ out)
{
    extern __shared__ unsigned char dynsmem[];
    uint2* sRing = reinterpret_cast<uint2*>(dynsmem);   // [TMAX], write-once

    __shared__ float sW[2][2][64];      // [warp][buf][class] prob rows
    __shared__ float sFm[NT * NSLOT];
    __shared__ int   sFe[NT];
    __shared__ int   sLast;

    const int task = blockIdx.x >> 5;   // 0 = error (C=4), 1 = phoneme (C=64)
    const int b    = blockIdx.x & 31;
    const int tid  = threadIdx.x;
    const int lane = tid & 31;
    const int wid  = tid >> 5;

    const float* logits;
    const int*   targets;
    int C, S, ilen, tlen;
    if (task == 0) {
        C = 4;  S = 50;
        logits  = elog + (size_t)b * TMAX * 4;
        targets = etgt + b * 50;
        ilen = eil[b]; tlen = etl[b];
    } else {
        C = 64; S = 200;
        logits  = plog + (size_t)b * TMAX * 64;
        targets = ptgt + b * 200;
        ilen = pil[b]; tlen = ptl[b];
    }
    const int L     = 2 * S + 1;
    const int Teff  = min(TMAX, max(ilen, 1));
    const int rlast = Teff - 1;
    const bool warpLive = (NSLOT * 32 * wid < L);

    // ---------- zero the ring + init finals ----------
    {
        uint4 z = make_uint4(0, 0, 0, 0);
        uint4* r4 = reinterpret_cast<uint4*>(sRing);
        for (int i = tid; i < TMAX / 2; i += NT) r4[i] = z;
    }
    #pragma unroll
    for (int j = 0; j < NSLOT; ++j) sFm[tid * NSLOT + j] = 0.f;
    sFe[tid] = 0;

    // ---------- per-thread symbol metadata: l = 8*tid + j ----------
    int   extc[NSYM];
    float skf[NSYM];
    #pragma unroll
    for (int k = 0; k < NSYM; ++k) {
        int s  = NSYM * tid + k;
        int sc = min(s, S - 1);
        int c1 = targets[sc];
        int c0 = targets[max(sc - 1, 0)];
        skf[k]  = (s >= 1 && c1 != c0) ? 1.f : 0.f;
        extc[k] = c1;
    }

    const int  kk  = 2 * lane;
    const bool kok = (kk < C);

    auto ldrow = [&](int r) -> float2 {
        float2 g = make_float2(0.f, 0.f);
        if (kok) g = *reinterpret_cast<const float2*>(logits + (size_t)r * C + kk);
        return g;
    };

    // ---------- state ----------
    float m[NSLOT];
    #pragma unroll
    for (int j = 0; j < NSLOT; ++j) m[j] = 0.f;
    int  e = 0;
    bool live = false;

    // ---------- prologue: row 0 init ----------
    {
        float2 g = ldrow(0);
        float u0 = kok ? ex2(g.x * LOG2E) : 0.f;
        float u1 = kok ? ex2(g.y * LOG2E) : 0.f;
        float ss = u0 + u1;
        #pragma unroll
        for (int o = 16; o; o >>= 1) ss += __shfl_xor_sync(0xffffffffu, ss, o);
        float r_ = rcpf(ss);
        int c1 = targets[0];
        float q0 = __shfl_sync(0xffffffffu, u0, c1 >> 1);
        float q1 = __shfl_sync(0xffffffffu, u1, c1 >> 1);
        if (tid == 0) {
            m[0] = u0 * r_;
            m[1] = ((c1 & 1) ? q1 : q0) * r_;
            live = true;
        }
    }

    // stage rows 1,2 into own sW; raw rows 3,4 in flight
    #pragma unroll
    for (int r0 = 1; r0 <= 2; ++r0) {
        float2 g = ldrow(min(r0, rlast));
        float u0 = kok ? ex2(g.x * LOG2E) : 0.f;
        float u1 = kok ? ex2(g.y * LOG2E) : 0.f;
        float ss = u0 + u1;
        #pragma unroll
        for (int o = 16; o; o >>= 1) ss += __shfl_xor_sync(0xffffffffu, ss, o);
        float r_ = rcpf(ss);
        if (kok) { sW[wid][r0 & 1][kk] = u0 * r_; sW[wid][r0 & 1][kk + 1] = u1 * r_; }
    }
    float2 y = ldrow(min(3, rlast));
    float2 z = ldrow(min(4, rlast));

    __syncthreads();   // ring zeroed + finals init + own sW rows visible

    // publish t=0 boundary state (warp0 lane31)
    if (wid == 0 && lane == 31) {
        asm volatile("st.volatile.shared.v2.u32 [%0], {%1,%2};"
                     :: "r"((unsigned)__cvta_generic_to_shared(sRing)),
                        "r"(__float_as_uint(m[NSLOT - 1]) | 0x80000000u),
                        "r"((unsigned)e));
    }

    if (warpLive && Teff > 1) {
        float pb = sW[wid][1][0];
        float p[NSYM];
        #pragma unroll
        for (int k = 0; k < NSYM; ++k) p[k] = sW[wid][1][extc[k]];

        const unsigned rbase = (unsigned)__cvta_generic_to_shared(sRing);
        unsigned rw = rbase + 8;          // write slot t (warp0)
        unsigned rr = rbase;              // read slot t-1 (warp1)

        for (int t = 1; t < Teff; ++t) {
            // (a) producer: probs for row t+2 -> own sW[t&1]
            float u0 = kok ? ex2(y.x * LOG2E) : 0.f;
            float u1 = kok ? ex2(y.y * LOG2E) : 0.f;
            float ss = u0 + u1;
            #pragma unroll
            for (int o = 16; o; o >>= 1) ss += __shfl_xor_sync(0xffffffffu, ss, o);
            float rr_ = rcpf(ss);
            if (kok) { sW[wid][t & 1][kk] = u0 * rr_; sW[wid][t & 1][kk + 1] = u1 * rr_; }

            // (b) raw LDG pipeline (3-iter lead)
            y = z;
            z = ldrow(min(t + 4, rlast));

            // (c) neighbor operand: left thread's OLD slot 7
            float nm = __shfl_up_sync(0xffffffffu, m[NSLOT - 1], 1);
            int   ne = __shfl_up_sync(0xffffffffu, e, 1);
            if (lane == 0) {
                if (wid == 1) {
                    unsigned lo, hi;
                    do {
                        asm volatile("ld.volatile.shared.v2.u32 {%0,%1}, [%2];"
                                     : "=r"(lo), "=r"(hi) : "r"(rr));
                    } while (lo == 0u);
                    nm = __uint_as_float(lo & 0x7FFFFFFFu);
                    ne = (int)hi;
                } else { nm = 0.f; ne = EMIN; }
            } else if (wid == 1) {
                // non-lane0 threads of warp1 still execute the poll (uniform
                // branch); their nm/ne come from the shuffle above.
                unsigned lo, hi;
                do {
                    asm volatile("ld.volatile.shared.v2.u32 {%0,%1}, [%2];"
                                 : "=r"(lo), "=r"(hi) : "r"(rr));
                } while (lo == 0u);
            }

            if (!live) e = ne;
            int d = ne - e;
            if (d > 100) {               // neighbor dominates: rebase (rare)
                float rb = pow2c(e - ne + 127);
                #pragma unroll
                for (int j = 0; j < NSLOT; ++j) m[j] *= rb;
                e = ne; d = 0;
            }
            float an = nm * pow2c(d + 127);

            // (d) recurrence (shared exponent basis e)
            float n[NSLOT];
            n[0] = pb   * (m[0] + an);
            n[1] = p[0] * fmaf(skf[0], an, m[1] + m[0]);
            #pragma unroll
            for (int k = 1; k < NSYM; ++k) {
                n[2 * k]     = pb   * (m[2 * k] + m[2 * k - 1]);
                n[2 * k + 1] = p[k] * fmaf(skf[k], m[2 * k - 1],
                                           m[2 * k + 1] + m[2 * k]);
            }
            #pragma unroll
            for (int j = 0; j < NSLOT; ++j) m[j] = n[j];

            // (e) renorm every 8 steps: max mantissa -> [1,2)
            if ((t & 7) == 0) {
                float mm = m[0];
                #pragma unroll
                for (int j = 1; j < NSLOT; ++j) mm = fmaxf(mm, m[j]);
                int bb = __float_as_int(mm);
                live = (bb != 0);
                int sh = live ? ((bb >> 23) - 127) : 0;
                float rs = __int_as_float(min(max(127 - sh, 1), 254) << 23);
                #pragma unroll
                for (int j = 0; j < NSLOT; ++j) m[j] *= rs;
                e += sh;
            }

            // publish state @ t (warp0 lane31)
            if (wid == 0 && lane == 31) {
                asm volatile("st.volatile.shared.v2.u32 [%0], {%1,%2};"
                             :: "r"(rw),
                                "r"(__float_as_uint(m[NSLOT - 1]) | 0x80000000u),
                                "r"((unsigned)e));
            }
            rw += 8; rr += 8;

            // (f) prefetch probs for t+1 from own staged row
            __syncwarp();
            {
                const float* wrow = sW[wid][(t + 1) & 1];
                pb = wrow[0];
                #pragma unroll
                for (int k = 0; k < NSYM; ++k) p[k] = wrow[extc[k]];
            }
        }
    }

    // ---------- publish finals ----------
    #pragma unroll
    for (int j = 0; j < NSLOT; ++j) sFm[tid * NSLOT + j] = m[j];
    sFe[tid] = e;
    __syncthreads();

    // ---------- loss + fused deterministic reduction ----------
    if (tid == 0) {
        const int iL = 2 * tlen - 1, iB = 2 * tlen;
        float mL = sFm[iL], mB = sFm[iB];
        int   eL = (mL > 0.f) ? sFe[iL / NSLOT] : EMIN;
        int   eB = (mB > 0.f) ? sFe[iB / NSLOT] : EMIN;
        int   em = max(eL, eB);
        float s2 = mL * pow2c(eL + 127 - em) + mB * pow2c(eB + 127 - em);
        float loss = (s2 > 0.f && em > EMIN / 2)
                   ? -((float)em + lg2(s2)) * LN2 : 0.f;
        if (!(loss <= 1e29f)) loss = 0.f;           // zero_infinity / NaN
        g_partial[blockIdx.x] = loss / (float)tlen * (1.0f / BATCH);
        __threadfence();
        unsigned tk = atomicAdd(&g_count, 1u);
        sLast = (tk == 63u);
    }
    __syncthreads();
    if (sLast && tid == 0) {
        __threadfence();
        float s = 0.f;
        #pragma unroll
        for (int i = 0; i < 64; ++i) {
            float v;
            asm volatile("ld.global.cg.f32 %0, [%1];" : "=f"(v) : "l"(g_partial + i));
            s += v;
        }
        out[0] = s;
        g_count = 0;   // reset for graph replay
    }
}

extern "C" void kernel_launch(void* const* d_in, const int* in_sizes, int n_in,
                              void* d_out, int out_size)
{
    const float* elog = (const float*)d_in[0];
    const float* plog = (const float*)d_in[1];
    const int*   etgt = (const int*)d_in[2];
    const int*   ptgt = (const int*)d_in[3];
    const int*   eil  = (const int*)d_in[4];
    const int*   pil  = (const int*)d_in[5];
    const int*   etl  = (const int*)d_in[6];
    const int*   ptl  = (const int*)d_in[7];
    float* out = (float*)d_out;

    cudaFuncSetAttribute(ctc_forward_kernel,
                         cudaFuncAttributeMaxDynamicSharedMemorySize, DYNSMEM);
    ctc_forward_kernel<<<64, NT, DYNSMEM>>>(elog, plog, etgt, ptgt,
                                            eil, pil, etl, ptl, out);
}